// round 1
// baseline (speedup 1.0000x reference)
#include <cuda_runtime.h>
#include <cuda_bf16.h>

// AddingGaussianBlur: x (64,512,512,3) f32, stds (64,) f32 -> out (64,512,512,3) f32
//
// Reference quirk: the 3x3 gaussian kernel k[i][j] depends ONLY on column j
// (both squared terms in the exponent use the same broadcast xs). After
// normalization the op is separable:
//   vertical  : unweighted 3-row sum (zero padded)
//   horizontal: weights [a, 1, a] / (3*(1+2a)),  a = exp(-1/s^2), s = 3*std[b]
//
// Strategy: one block per (batch, 16-row band). 3-row smem ring buffer so each
// input row is read from DRAM once per band (traffic ratio 18/16). Coalesced
// scalar loads (512 threads x 3 floats cover the 1536-float row).

#define H 512
#define W 512
#define C 3
#define ROWW (W * C)          // 1536 floats per image row
#define NTHREADS 512
#define ROWS_PER_BLOCK 16

__global__ __launch_bounds__(NTHREADS)
void gauss_blur_kernel(const float* __restrict__ x,
                       const float* __restrict__ stds,
                       float* __restrict__ out)
{
    __shared__ float ring[3][ROWW];
    __shared__ float vsum[ROWW];

    const int b    = blockIdx.y;
    const int i0   = blockIdx.x * ROWS_PER_BLOCK;
    const int tid  = threadIdx.x;

    // Per-batch coefficients
    const float s   = stds[b] * 3.0f;
    const float a   = expf(-1.0f / (s * s));
    const float inv = 1.0f / (3.0f * (1.0f + 2.0f * a));

    const float* __restrict__ xb = x   + (size_t)b * H * ROWW;
    float*       __restrict__ ob = out + (size_t)b * H * ROWW;

    // Load a global row (or zeros if out of range) into a ring slot.
    // Strided so consecutive threads touch consecutive addresses (coalesced).
    auto loadrow = [&](int gi, int slot) {
        if (gi >= 0 && gi < H) {
            const float* r = xb + (size_t)gi * ROWW;
            #pragma unroll
            for (int k = 0; k < ROWW / NTHREADS; k++)
                ring[slot][tid + k * NTHREADS] = r[tid + k * NTHREADS];
        } else {
            #pragma unroll
            for (int k = 0; k < ROWW / NTHREADS; k++)
                ring[slot][tid + k * NTHREADS] = 0.0f;
        }
    };

    // Preload rows i0-1 (slot 0) and i0 (slot 1)
    loadrow(i0 - 1, 0);
    loadrow(i0,     1);

    #pragma unroll 1
    for (int r = 0; r < ROWS_PER_BLOCK; r++) {
        const int gi = i0 + r;

        // Bring in row gi+1. Slot map at iteration r:
        //   gi-1 -> r%3, gi -> (r+1)%3, gi+1 -> (r+2)%3
        loadrow(gi + 1, (r + 2) % 3);
        __syncthreads();

        const float* r0 = ring[(r + 0) % 3];
        const float* r1 = ring[(r + 1) % 3];
        const float* r2 = ring[(r + 2) % 3];

        #pragma unroll
        for (int k = 0; k < ROWW / NTHREADS; k++) {
            const int e = tid + k * NTHREADS;
            vsum[e] = r0[e] + r1[e] + r2[e];
        }
        __syncthreads();

        float* orow = ob + (size_t)gi * ROWW;
        #pragma unroll
        for (int k = 0; k < ROWW / NTHREADS; k++) {
            const int e = tid + k * NTHREADS;
            const float l  = (e >= C)        ? vsum[e - C] : 0.0f;
            const float rr = (e < ROWW - C)  ? vsum[e + C] : 0.0f;
            orow[e] = inv * (a * (l + rr) + vsum[e]);
        }
        // No trailing sync needed: next iteration's smem writes happen after
        // its own __syncthreads(), which orders this iteration's reads first.
    }
}

extern "C" void kernel_launch(void* const* d_in, const int* in_sizes, int n_in,
                              void* d_out, int out_size)
{
    const float* x    = (const float*)d_in[0];
    const float* stds = (const float*)d_in[1];
    float* out        = (float*)d_out;

    dim3 grid(H / ROWS_PER_BLOCK, 64);  // (32, 64)
    gauss_blur_kernel<<<grid, NTHREADS>>>(x, stds, out);
}

// round 2
// speedup vs baseline: 1.1827x; 1.1827x over previous
#include <cuda_runtime.h>
#include <cuda_bf16.h>

// AddingGaussianBlur: x (64,512,512,3) f32, stds (64,) f32 -> out f32 same shape.
//
// Reference quirk: the 3x3 kernel depends only on the column index, so the op
// is separable into
//   vertical  : unweighted 3-row sum (zero padded)
//   horizontal: [a, 1, a] / (3*(1+2a)),  a = exp(-1/s^2), s = 3*std[b]
//
// R2 design (fix L1-bound kernel from R1):
//  - vertical 3-row window lives in registers (float4 per thread, rolling),
//    no ring smem at all
//  - smem used only to exchange the horizontal +-3 taps: one STS.128 +
//    two aligned LDS.128 per float4, halo-padded, double buffered (1 sync/row)
//  - global traffic fully 128-bit, row gi+2 prefetched one iteration ahead

#define H       512
#define ROWW    1536            // 512 * 3 floats per image row
#define NT      384             // 384 threads x float4 = one row
#define RPB     32              // rows per block band
#define PAD     4               // float halo each side (one float4)

__global__ __launch_bounds__(NT)
void gauss_blur_kernel(const float* __restrict__ x,
                       const float* __restrict__ stds,
                       float* __restrict__ out)
{
    __shared__ float vs[2][ROWW + 2 * PAD];

    const int b  = blockIdx.y;
    const int i0 = blockIdx.x * RPB;
    const int t  = threadIdx.x;

    // zero the halos once (visible after the first __syncthreads below)
    if (t < PAD) {
        vs[0][t] = 0.0f; vs[0][ROWW + PAD + t] = 0.0f;
        vs[1][t] = 0.0f; vs[1][ROWW + PAD + t] = 0.0f;
    }

    const float s   = stds[b] * 3.0f;
    const float a   = expf(-1.0f / (s * s));
    const float inv = 1.0f / (3.0f * (1.0f + 2.0f * a));

    const float* __restrict__ xb = x   + (size_t)b * H * ROWW;
    float*       __restrict__ ob = out + (size_t)b * H * ROWW;

    auto ld = [&](int gi) -> float4 {
        if ((unsigned)gi < (unsigned)H)
            return reinterpret_cast<const float4*>(xb + (size_t)gi * ROWW)[t];
        return make_float4(0.0f, 0.0f, 0.0f, 0.0f);
    };

    // rolling vertical window: rm = row gi-1, rc = row gi, rp = row gi+1
    float4 rm = ld(i0 - 1);
    float4 rc = ld(i0);
    float4 rp = ld(i0 + 1);

    int par = 0;
    #pragma unroll 1
    for (int r = 0; r < RPB; r++) {
        const int gi = i0 + r;

        // prefetch row gi+2 (consumed next iteration -> latency hidden)
        float4 rn = ld(gi + 2);

        // vertical sum in registers
        float4 v;
        v.x = rm.x + rc.x + rp.x;
        v.y = rm.y + rc.y + rp.y;
        v.z = rm.z + rc.z + rp.z;
        v.w = rm.w + rc.w + rp.w;

        // publish vsum chunk (STS.128), aligned: PAD + 4t
        reinterpret_cast<float4*>(vs[par] + PAD)[t] = v;
        __syncthreads();

        // neighbor chunks, both 16B aligned:
        //   L = vsum[4t-4 .. 4t-1]   at vs[par] + 4t
        //   R = vsum[4t+4 .. 4t+7]   at vs[par] + PAD+4 + 4t
        const float4 L  = reinterpret_cast<const float4*>(vs[par])[t];
        const float4 Rr = reinterpret_cast<const float4*>(vs[par] + PAD + 4)[t];

        // out[j] = inv * (a*(vsum[e-3] + vsum[e+3]) + vsum[e]),  e = 4t+j
        float4 o;
        o.x = inv * (a * (L.y + v.w ) + v.x);
        o.y = inv * (a * (L.z + Rr.x) + v.y);
        o.z = inv * (a * (L.w + Rr.y) + v.z);
        o.w = inv * (a * (v.x + Rr.z) + v.w);

        reinterpret_cast<float4*>(ob + (size_t)gi * ROWW)[t] = o;

        // rotate window, flip vsum buffer (double buffer -> 1 sync/row)
        rm = rc; rc = rp; rp = rn;
        par ^= 1;
    }
}

extern "C" void kernel_launch(void* const* d_in, const int* in_sizes, int n_in,
                              void* d_out, int out_size)
{
    const float* x    = (const float*)d_in[0];
    const float* stds = (const float*)d_in[1];
    float* out        = (float*)d_out;

    dim3 grid(H / RPB, 64);   // (16, 64) = 1024 blocks
    gauss_blur_kernel<<<grid, NT>>>(x, stds, out);
}

// round 3
// speedup vs baseline: 1.3104x; 1.1079x over previous
#include <cuda_runtime.h>
#include <cuda_bf16.h>

// AddingGaussianBlur: x (64,512,512,3) f32, stds (64,) f32 -> out f32.
//
// Separable (reference's 3x3 kernel depends only on column index):
//   vertical  : unweighted 3-row sum (zero padded)
//   horizontal: [a, 1, a] / (3*(1+2a)),  a = exp(-1/s^2), s = 3*std[b]
//
// R3: 2 rows per iteration (2 outstanding LDG.128/thread for MLP, half the
// barriers), register rolling window, smem only for the +-3 horizontal
// exchange (halo-padded, double-buffered pairs), streaming stores.

#define H       512
#define ROWW    1536            // 512 * 3 floats per image row
#define NT      384             // 384 threads x float4 = one row
#define RPB     32              // rows per block band
#define PAD     4               // float halo each side (one float4)
#define SROW    (ROWW + 2 * PAD)

__global__ __launch_bounds__(NT)
void gauss_blur_kernel(const float* __restrict__ x,
                       const float* __restrict__ stds,
                       float* __restrict__ out)
{
    __shared__ float vs[4][SROW];

    const int b  = blockIdx.y;
    const int i0 = blockIdx.x * RPB;
    const int t  = threadIdx.x;

    // zero halos of all 4 buffers (threads 0..15: buf = t/4, idx = t%4)
    if (t < 16) {
        const int buf = t >> 2, idx = t & 3;
        vs[buf][idx] = 0.0f;
        vs[buf][ROWW + PAD + idx] = 0.0f;
    }

    const float s   = stds[b] * 3.0f;
    const float a   = expf(-1.0f / (s * s));
    const float inv = 1.0f / (3.0f * (1.0f + 2.0f * a));

    const float* __restrict__ xb = x   + (size_t)b * H * ROWW;
    float*       __restrict__ ob = out + (size_t)b * H * ROWW;

    auto ld = [&](int gi) -> float4 {
        if ((unsigned)gi < (unsigned)H)
            return reinterpret_cast<const float4*>(xb + (size_t)gi * ROWW)[t];
        return make_float4(0.0f, 0.0f, 0.0f, 0.0f);
    };

    // rolling window: rm=gi-1, rc=gi, rp=gi+1, rq=gi+2
    float4 rm = ld(i0 - 1);
    float4 rc = ld(i0);
    float4 rp = ld(i0 + 1);
    float4 rq = ld(i0 + 2);

    int par = 0;
    #pragma unroll 1
    for (int r = 0; r < RPB; r += 2) {
        const int gi = i0 + r;

        // prefetch rows gi+3, gi+4 (consumed at rotation below)
        const float4 ra = ld(gi + 3);
        const float4 rb = ld(gi + 4);

        // vertical sums for output rows gi and gi+1
        float4 v0, v1;
        v0.x = rm.x + rc.x + rp.x;  v1.x = rc.x + rp.x + rq.x;
        v0.y = rm.y + rc.y + rp.y;  v1.y = rc.y + rp.y + rq.y;
        v0.z = rm.z + rc.z + rp.z;  v1.z = rc.z + rp.z + rq.z;
        v0.w = rm.w + rc.w + rp.w;  v1.w = rc.w + rp.w + rq.w;

        float* s0 = vs[par * 2];
        float* s1 = vs[par * 2 + 1];
        reinterpret_cast<float4*>(s0 + PAD)[t] = v0;
        reinterpret_cast<float4*>(s1 + PAD)[t] = v1;
        __syncthreads();

        // neighbor chunks (16B aligned): L = vsum[4t-4..4t-1], R = vsum[4t+4..4t+7]
        const float4 L0 = reinterpret_cast<const float4*>(s0)[t];
        const float4 R0 = reinterpret_cast<const float4*>(s0 + PAD + 4)[t];
        const float4 L1 = reinterpret_cast<const float4*>(s1)[t];
        const float4 R1 = reinterpret_cast<const float4*>(s1 + PAD + 4)[t];

        // out[e] = inv * (a*(vsum[e-3] + vsum[e+3]) + vsum[e]),  e = 4t+j
        float4 o0, o1;
        o0.x = inv * (a * (L0.y + v0.w) + v0.x);
        o0.y = inv * (a * (L0.z + R0.x) + v0.y);
        o0.z = inv * (a * (L0.w + R0.y) + v0.z);
        o0.w = inv * (a * (v0.x + R0.z) + v0.w);

        o1.x = inv * (a * (L1.y + v1.w) + v1.x);
        o1.y = inv * (a * (L1.z + R1.x) + v1.y);
        o1.z = inv * (a * (L1.w + R1.y) + v1.z);
        o1.w = inv * (a * (v1.x + R1.z) + v1.w);

        __stcs(&reinterpret_cast<float4*>(ob + (size_t)gi      * ROWW)[t], o0);
        __stcs(&reinterpret_cast<float4*>(ob + (size_t)(gi + 1) * ROWW)[t], o1);

        // rotate window by 2 rows; flip smem buffer pair
        rm = rp; rc = rq; rp = ra; rq = rb;
        par ^= 1;
    }
}

extern "C" void kernel_launch(void* const* d_in, const int* in_sizes, int n_in,
                              void* d_out, int out_size)
{
    const float* x    = (const float*)d_in[0];
    const float* stds = (const float*)d_in[1];
    float* out        = (float*)d_out;

    dim3 grid(H / RPB, 64);   // (16, 64) = 1024 blocks
    gauss_blur_kernel<<<grid, NT>>>(x, stds, out);
}